// round 9
// baseline (speedup 1.0000x reference)
#include <cuda_runtime.h>
#include <cstdint>
#include <math.h>

// Problem constants (fixed by the dataset problem)
#define BATCH  16
#define NPTS   6890
#define NBUCK  2048
#define BSCALE 128.0f          // buckets per unit x: range [-8, 8) -> 2048
#define BOFF   8.0f

#define TPB    256
#define BPB    27              // 27 * 256 = 6912 >= 6890
#define NBLK5  (BPB * BATCH)   // prune grid = 432 blocks

#define BSAMP  4               // bound samples every 4th row
#define BPB4   7               // 7 * 256 = 1792 >= ceil(6890/4)

// ---- persistent device state (static globals; no allocation) ----
// Entry invariant (restored every run): g_hist == 0, g_arr == 0,
// g_bound_i == g_min_i == +inf bits.
__device__ int    g_hist[2][BATCH][NBUCK];        // zero-init; k2 re-zeroes
__device__ int    g_bstart[2][BATCH][NBUCK + 1];
__device__ int    g_cursor[2][BATCH][NBUCK];
__device__ float4 g_pts[2][BATCH][NPTS];          // sorted clouds: (x,y,z,||.||^2)
__device__ int    g_bound_i = 0x7F800000;         // +inf bits (k5 resets)
__device__ int    g_min_i   = 0x7F800000;         // +inf bits (k5 resets)
__device__ int    g_arr;                          // zero-init  (k5 resets)

__device__ __forceinline__ int bucket_of(float x) {
    int b = (int)((x + BOFF) * BSCALE);           // monotone map
    return min(max(b, 0), NBUCK - 1);
}

// window min with 4 independent accumulators (MLP=4)
__device__ __forceinline__ float window_min(const float4* __restrict__ P,
                                            int lo, int hi,
                                            float nx, float ny, float nz)
{
    float m0 = INFINITY, m1 = INFINITY, m2 = INFINITY, m3 = INFINITY;
    int t = lo;
    for (; t + 4 <= hi; t += 4) {
        float4 q0 = P[t], q1 = P[t + 1], q2 = P[t + 2], q3 = P[t + 3];
        float d0 = fmaf(nx, q0.x, q0.w); d0 = fmaf(ny, q0.y, d0); d0 = fmaf(nz, q0.z, d0);
        float d1 = fmaf(nx, q1.x, q1.w); d1 = fmaf(ny, q1.y, d1); d1 = fmaf(nz, q1.z, d1);
        float d2 = fmaf(nx, q2.x, q2.w); d2 = fmaf(ny, q2.y, d2); d2 = fmaf(nz, q2.z, d2);
        float d3 = fmaf(nx, q3.x, q3.w); d3 = fmaf(ny, q3.y, d3); d3 = fmaf(nz, q3.z, d3);
        m0 = fminf(m0, d0); m1 = fminf(m1, d1);
        m2 = fminf(m2, d2); m3 = fminf(m3, d3);
    }
    for (; t < hi; t++) {
        float4 q = P[t];
        float d = fmaf(nx, q.x, q.w); d = fmaf(ny, q.y, d); d = fmaf(nz, q.z, d);
        m0 = fminf(m0, d);
    }
    return fminf(fminf(m0, m1), fminf(m2, m3));
}

// ============================================================
// k1: x-histogram of both clouds
// ============================================================
__global__ __launch_bounds__(TPB) void k1_hist(
    const float* __restrict__ v1, const float* __restrict__ v2)
{
    const int cloud = blockIdx.z;
    const int b = blockIdx.y;
    const int i = blockIdx.x * TPB + threadIdx.x;
    if (i < NPTS) {
        const float* src = cloud ? v2 : v1;
        float x = src[((size_t)b * NPTS + i) * 3];
        atomicAdd(&g_hist[cloud][b][bucket_of(x)], 1);
    }
}

// ============================================================
// k2: per-(cloud,batch) exclusive scan; zero hist behind itself
// ============================================================
__global__ __launch_bounds__(1024) void k2_scan()
{
    __shared__ int warpsum[32];
    const int b = blockIdx.x, cloud = blockIdx.y;
    const int tid = threadIdx.x, lane = tid & 31, wid = tid >> 5;

    int a0 = g_hist[cloud][b][2 * tid], a1 = g_hist[cloud][b][2 * tid + 1];
    g_hist[cloud][b][2 * tid] = 0; g_hist[cloud][b][2 * tid + 1] = 0;
    int s = a0 + a1;
    int v = s;
#pragma unroll
    for (int o = 1; o < 32; o <<= 1) {
        int t = __shfl_up_sync(0xFFFFFFFFu, v, o);
        if (lane >= o) v += t;
    }
    if (lane == 31) warpsum[wid] = v;
    __syncthreads();
    if (wid == 0) {
        int w = warpsum[lane];
#pragma unroll
        for (int o = 1; o < 32; o <<= 1) {
            int t = __shfl_up_sync(0xFFFFFFFFu, w, o);
            if (lane >= o) w += t;
        }
        warpsum[lane] = w;
    }
    __syncthreads();
    int excl = v - s + ((wid > 0) ? warpsum[wid - 1] : 0);
    g_bstart[cloud][b][2 * tid]     = excl;
    g_bstart[cloud][b][2 * tid + 1] = excl + a0;
    g_cursor[cloud][b][2 * tid]     = excl;
    g_cursor[cloud][b][2 * tid + 1] = excl + a0;
    if (tid == 0) g_bstart[cloud][b][NBUCK] = NPTS;
}

// ============================================================
// k3: scatter both clouds into x-sorted float4 arrays
// ============================================================
__global__ __launch_bounds__(TPB) void k3_scatter(
    const float* __restrict__ v1, const float* __restrict__ v2)
{
    const int cloud = blockIdx.z;
    const int b = blockIdx.y;
    const int i = blockIdx.x * TPB + threadIdx.x;
    if (i < NPTS) {
        const float* src = cloud ? v2 : v1;
        const float* q = src + ((size_t)b * NPTS + i) * 3;
        float x = q[0], y = q[1], z = q[2];
        float qn = fmaf(z, z, fmaf(y, y, x * x));
        int pos = atomicAdd(&g_cursor[cloud][b][bucket_of(x)], 1);
        g_pts[cloud][b][pos] = make_float4(x, y, z, qn);
    }
}

// ============================================================
// k4: upper bound via sorted-x neighbors of every 4th row
// ============================================================
__global__ __launch_bounds__(TPB) void k4_bound()
{
    const int b = blockIdx.y;
    const int i = (blockIdx.x * TPB + threadIdx.x) * BSAMP;

    float vmin = INFINITY;
    if (i < NPTS) {
        float4 p = g_pts[0][b][i];
        float nx = -2.f * p.x, ny = -2.f * p.y, nz = -2.f * p.z;
        int bk = bucket_of(p.x);
        int lo = max(g_bstart[1][b][bk] - 8, 0);
        int hi = min(g_bstart[1][b][bk + 1] + 8, NPTS);
        vmin = p.w + window_min(g_pts[1][b], lo, hi, nx, ny, nz);
    }
    // full-warp reduce (no divergent shfl)
#pragma unroll
    for (int o = 16; o; o >>= 1)
        vmin = fminf(vmin, __shfl_xor_sync(0xFFFFFFFFu, vmin, o));
    if ((threadIdx.x & 31) == 0 && vmin < INFINITY)
        atomicMin(&g_bound_i, __float_as_int(vmin));
}

// ============================================================
// k5: per-thread pruned exact pass + output + state reset
// ============================================================
__global__ __launch_bounds__(TPB) void k5_prune(float* __restrict__ out)
{
    const int b = blockIdx.y;
    const int i = blockIdx.x * TPB + threadIdx.x;
    const int tid = threadIdx.x, lane = tid & 31, wid = tid >> 5;

    float usq = __int_as_float(g_bound_i);
    // slack covers fp32 dot-form cancellation (<=~2e-5 at these magnitudes)
    float U = sqrtf(fmaxf(usq, 0.f) + 3e-5f) * 1.0005f;

    float vmin = INFINITY;
    if (i < NPTS) {
        float4 p = g_pts[0][b][i];
        float nx = -2.f * p.x, ny = -2.f * p.y, nz = -2.f * p.z;
        int lo = g_bstart[1][b][bucket_of(p.x - U)];
        int hi = g_bstart[1][b][bucket_of(p.x + U) + 1];
        vmin = p.w + window_min(g_pts[1][b], lo, hi, nx, ny, nz);
    }

#pragma unroll
    for (int o = 16; o; o >>= 1)
        vmin = fminf(vmin, __shfl_xor_sync(0xFFFFFFFFu, vmin, o));
    __shared__ float smin[TPB / 32];
    if (lane == 0) smin[wid] = vmin;
    __syncthreads();
    if (tid == 0) {
        float t = smin[0];
#pragma unroll
        for (int w = 1; w < TPB / 32; w++) t = fminf(t, smin[w]);
        if (t < INFINITY)
            atomicMin(&g_min_i, __float_as_int(t));
        __threadfence();
        int a = atomicAdd(&g_arr, 1);
        if (a == NBLK5 - 1) {                    // last block: emit + reset state
            int mb = atomicAdd(&g_min_i, 0);     // coherent read
            out[0] = sqrtf(fmaxf(__int_as_float(mb), 0.f));
            g_min_i   = 0x7F800000;
            g_bound_i = 0x7F800000;
            g_arr = 0;
        }
    }
}

extern "C" void kernel_launch(void* const* d_in, const int* in_sizes, int n_in,
                              void* d_out, int out_size)
{
    const float* v1 = (const float*)d_in[0];
    const float* v2 = (const float*)d_in[1];
    float* out = (float*)d_out;

    dim3 gh(BPB, BATCH, 2);
    k1_hist<<<gh, TPB>>>(v1, v2);
    dim3 gs(BATCH, 2);
    k2_scan<<<gs, 1024>>>();
    k3_scatter<<<gh, TPB>>>(v1, v2);
    dim3 gb(BPB4, BATCH);
    k4_bound<<<gb, TPB>>>();
    dim3 gp(BPB, BATCH);
    k5_prune<<<gp, TPB>>>(out);
}

// round 10
// speedup vs baseline: 1.3781x; 1.3781x over previous
#include <cuda_runtime.h>
#include <cstdint>
#include <math.h>

// Problem constants (fixed by the dataset problem)
#define BATCH  16
#define NPTS   6890
#define NBUCK  2048
#define BSCALE 128.0f           // buckets per unit x: range [-8, 8) -> 2048
#define BOFF   8.0f

#define TPB     1024
#define BPB     9               // blocks per batch
#define NBLK    (BATCH * BPB)   // 144 <= 148 SMs -> co-resident at 1 CTA/SM
#define ROWS_PB 768             // 9 * 768 = 6912 >= 6890

// ---- persistent device state (static globals; no allocation) ----
// g_hist: zero at entry (scan re-zeroes). g_pbar: phase-accumulating, never reset.
// g_min_i/g_arr: reset by the globally-last block. g_bbound: re-inited in P1.
__device__ int          g_hist[2][BATCH][NBUCK];
__device__ int          g_bstart[2][BATCH][NBUCK + 1];
__device__ int          g_cursor[2][BATCH][NBUCK];
__device__ float4       g_pts[2][BATCH][NPTS];     // sorted: (x, y, z, ||.||^2)
__device__ int          g_bbound[BATCH];           // per-batch bound bits
__device__ int          g_min_i = 0x7F800000;      // +inf bits
__device__ unsigned int g_pbar[BATCH][4];          // per-batch phase barriers
__device__ int          g_arr;                     // global arrival counter

__device__ __forceinline__ int bucket_of(float x) {
    int b = (int)((x + BOFF) * BSCALE);            // monotone map
    return min(max(b, 0), NBUCK - 1);
}

// Per-batch barrier: count in bits[0:8), phase in bits[8:32). Last of BPB
// arrivers rolls the count to 0 and bumps the phase; spinners wait for the
// phase to move. No reset between replays (phase accumulates) -> replay-safe.
__device__ __forceinline__ void pbar(int b, int k) {
    __syncthreads();
    if (threadIdx.x == 0) {
        __threadfence();
        unsigned int t = atomicAdd(&g_pbar[b][k], 1u);
        if ((t & 0xFFu) == (BPB - 1)) {
            atomicAdd(&g_pbar[b][k], 0x100u - BPB);   // count->0, phase+1
        } else {
            unsigned int ph = t >> 8;
            while ((atomicAdd(&g_pbar[b][k], 0u) >> 8) == ph) __nanosleep(64);
        }
        __threadfence();
    }
    __syncthreads();
}

// window min of (||q||^2 - 2 p.q) with 4 independent accumulators (MLP=4)
__device__ __forceinline__ float window_min(const float4* __restrict__ P,
                                            int lo, int hi,
                                            float nx, float ny, float nz)
{
    float m0 = INFINITY, m1 = INFINITY, m2 = INFINITY, m3 = INFINITY;
    int t = lo;
    for (; t + 4 <= hi; t += 4) {
        float4 q0 = P[t], q1 = P[t + 1], q2 = P[t + 2], q3 = P[t + 3];
        float d0 = fmaf(nx, q0.x, q0.w); d0 = fmaf(ny, q0.y, d0); d0 = fmaf(nz, q0.z, d0);
        float d1 = fmaf(nx, q1.x, q1.w); d1 = fmaf(ny, q1.y, d1); d1 = fmaf(nz, q1.z, d1);
        float d2 = fmaf(nx, q2.x, q2.w); d2 = fmaf(ny, q2.y, d2); d2 = fmaf(nz, q2.z, d2);
        float d3 = fmaf(nx, q3.x, q3.w); d3 = fmaf(ny, q3.y, d3); d3 = fmaf(nz, q3.z, d3);
        m0 = fminf(m0, d0); m1 = fminf(m1, d1);
        m2 = fminf(m2, d2); m3 = fminf(m3, d3);
    }
    for (; t < hi; t++) {
        float4 q = P[t];
        float d = fmaf(nx, q.x, q.w); d = fmaf(ny, q.y, d); d = fmaf(nz, q.z, d);
        m0 = fminf(m0, d);
    }
    return fminf(fminf(m0, m1), fminf(m2, m3));
}

__global__ __launch_bounds__(TPB, 1) void fused_kernel(
    const float* __restrict__ v1,
    const float* __restrict__ v2,
    float* __restrict__ out)
{
    const int b   = blockIdx.x / BPB;
    const int s   = blockIdx.x % BPB;
    const int tid = threadIdx.x, lane = tid & 31, wid = tid >> 5;
    const int row = s * ROWS_PB + tid;
    const bool rowact = (tid < ROWS_PB) && (row < NPTS);

    __shared__ int   warpsum[32];
    __shared__ float smin[TPB / 32];

    // ---------- P1: x-histogram of both clouds; re-init batch bound ----------
    if (s == 0 && tid == 0) g_bbound[b] = 0x7F800000;
    if (rowact) {
        float x1 = v1[((size_t)b * NPTS + row) * 3];
        atomicAdd(&g_hist[0][b][bucket_of(x1)], 1);
        float x2 = v2[((size_t)b * NPTS + row) * 3];
        atomicAdd(&g_hist[1][b][bucket_of(x2)], 1);
    }
    pbar(b, 0);

    // ---------- P2: scan (block s=0 -> cloud 0, s=1 -> cloud 1); zero hist ----------
    if (s < 2) {
        const int cloud = s;
        int a0 = g_hist[cloud][b][2 * tid], a1 = g_hist[cloud][b][2 * tid + 1];
        g_hist[cloud][b][2 * tid] = 0; g_hist[cloud][b][2 * tid + 1] = 0;
        int sum = a0 + a1;
        int v = sum;
#pragma unroll
        for (int o = 1; o < 32; o <<= 1) {
            int t = __shfl_up_sync(0xFFFFFFFFu, v, o);
            if (lane >= o) v += t;
        }
        if (lane == 31) warpsum[wid] = v;
        __syncthreads();
        if (wid == 0) {
            int w = warpsum[lane];
#pragma unroll
            for (int o = 1; o < 32; o <<= 1) {
                int t = __shfl_up_sync(0xFFFFFFFFu, w, o);
                if (lane >= o) w += t;
            }
            warpsum[lane] = w;
        }
        __syncthreads();
        int excl = v - sum + ((wid > 0) ? warpsum[wid - 1] : 0);
        g_bstart[cloud][b][2 * tid]     = excl;
        g_bstart[cloud][b][2 * tid + 1] = excl + a0;
        g_cursor[cloud][b][2 * tid]     = excl;
        g_cursor[cloud][b][2 * tid + 1] = excl + a0;
        if (tid == 0) g_bstart[cloud][b][NBUCK] = NPTS;
    }
    pbar(b, 1);

    // ---------- P3: scatter both clouds into sorted float4 arrays ----------
    if (rowact) {
#pragma unroll
        for (int cloud = 0; cloud < 2; cloud++) {
            const float* src = cloud ? v2 : v1;
            const float* q = src + ((size_t)b * NPTS + row) * 3;
            float x = q[0], y = q[1], z = q[2];
            float qn = fmaf(z, z, fmaf(y, y, x * x));
            int pos = atomicAdd(&g_cursor[cloud][b][bucket_of(x)], 1);
            g_pts[cloud][b][pos] = make_float4(x, y, z, qn);
        }
    }
    pbar(b, 2);

    // ---------- P4: 3-bucket neighborhood pass (bound + bulk of prune) ----------
    float4 p = make_float4(0.f, 0.f, 0.f, 0.f);
    float nx = 0.f, ny = 0.f, nz = 0.f;
    int lo1 = 0, hi1 = 0;
    float vm = INFINITY;
    if (rowact) {
        p = g_pts[0][b][row];
        nx = -2.f * p.x; ny = -2.f * p.y; nz = -2.f * p.z;
        int bk = bucket_of(p.x);
        lo1 = g_bstart[1][b][max(bk - 1, 0)];
        hi1 = g_bstart[1][b][min(bk + 1, NBUCK - 1) + 1];
        float m = window_min(g_pts[1][b], lo1, hi1, nx, ny, nz);
        vm = p.w + m;                                // may be +inf if window empty
    }
    {   // full-warp + block reduce (inactive lanes contribute INF)
        float t = vm;
#pragma unroll
        for (int o = 16; o; o >>= 1) t = fminf(t, __shfl_xor_sync(0xFFFFFFFFu, t, o));
        if (lane == 0) smin[wid] = t;
        __syncthreads();
        if (tid == 0) {
            float r = smin[0];
#pragma unroll
            for (int w = 1; w < TPB / 32; w++) r = fminf(r, smin[w]);
            if (r < INFINITY) atomicMin(&g_bbound[b], __float_as_int(r));
        }
    }
    pbar(b, 3);

    // ---------- P5: rare window extension + global reduce + output ----------
    {
        float usq = __int_as_float(g_bbound[b]);
        // slack covers fp32 dot-form cancellation at these magnitudes
        float U = sqrtf(fmaxf(usq, 0.f) + 3e-5f) * 1.0005f;
        if (rowact) {
            int lo2 = g_bstart[1][b][bucket_of(p.x - U)];
            int hi2 = g_bstart[1][b][bucket_of(p.x + U) + 1];
            if (lo2 < lo1)
                vm = fminf(vm, p.w + window_min(g_pts[1][b], lo2, lo1, nx, ny, nz));
            if (hi2 > hi1)
                vm = fminf(vm, p.w + window_min(g_pts[1][b], hi1, hi2, nx, ny, nz));
        }
#pragma unroll
        for (int o = 16; o; o >>= 1) vm = fminf(vm, __shfl_xor_sync(0xFFFFFFFFu, vm, o));
        __syncthreads();                      // smin reuse
        if (lane == 0) smin[wid] = vm;
        __syncthreads();
        if (tid == 0) {
            float r = smin[0];
#pragma unroll
            for (int w = 1; w < TPB / 32; w++) r = fminf(r, smin[w]);
            if (r < INFINITY) atomicMin(&g_min_i, __float_as_int(r));
            __threadfence();
            int a = atomicAdd(&g_arr, 1);
            if (a == NBLK - 1) {             // globally last block: emit + reset
                int mb = atomicAdd(&g_min_i, 0);
                out[0] = sqrtf(fmaxf(__int_as_float(mb), 0.f));
                g_min_i = 0x7F800000;
                g_arr = 0;
            }
        }
    }
}

extern "C" void kernel_launch(void* const* d_in, const int* in_sizes, int n_in,
                              void* d_out, int out_size)
{
    const float* v1 = (const float*)d_in[0];
    const float* v2 = (const float*)d_in[1];
    float* out = (float*)d_out;

    fused_kernel<<<NBLK, TPB>>>(v1, v2, out);
}